// round 3
// baseline (speedup 1.0000x reference)
#include <cuda_runtime.h>

#define NU 80000
#define NI 30000
#define NT 110000   // NU + NI
#define DD 64
#define NNZ_ADJ 2000000
#define NNZ_MM  300000

#define ADJ_CAP 64   // Poisson(18.2) max-degree bound over 110K rows (>10 sigma)
#define MM_CAP  48   // Poisson(10.0) max-degree bound over 30K rows  (>10 sigma)

// out layout (float offsets)
#define OFF_UG   0
#define OFF_IG   (NU*DD)
#define OFF_IMG  (OFF_IG + NI*DD)
#define OFF_TXT  (OFF_IMG + NI*DD)
#define OFF_H    (OFF_TXT + NI*DD)

// ---------------- scratch (__device__ globals; no allocation allowed) ----------------
__device__ float g_ego[NT*DD];      // [user_emb ; item_emb]
__device__ float g_cur1[NT*DD];     // layer-1 adj output
__device__ float g_ipre[NI*DD];     // (ie + cur1 + cur2)/3 for items
__device__ float g_hnorm[NI*DD];

__device__ int  g_cnt[NT + 2*NI];   // adj | img | txt counters (single memset)
__device__ int2 g_adj_pairs[(size_t)NT * ADJ_CAP];
__device__ int2 g_img_pairs[(size_t)NI * MM_CAP];
__device__ int2 g_txt_pairs[(size_t)NI * MM_CAP];

// ---------------- bucket build: 4 edges per thread, 4 atomics in flight ----------------
__device__ __forceinline__ void bucket4(int4 r, int4 c, float4 v,
                                        int* __restrict__ counts, int2* __restrict__ pairs,
                                        int cap) {
    int p0 = atomicAdd(&counts[r.x], 1);
    int p1 = atomicAdd(&counts[r.y], 1);
    int p2 = atomicAdd(&counts[r.z], 1);
    int p3 = atomicAdd(&counts[r.w], 1);
    if (p0 < cap) pairs[(size_t)r.x * cap + p0] = make_int2(c.x, __float_as_int(v.x));
    if (p1 < cap) pairs[(size_t)r.y * cap + p1] = make_int2(c.y, __float_as_int(v.y));
    if (p2 < cap) pairs[(size_t)r.z * cap + p2] = make_int2(c.z, __float_as_int(v.z));
    if (p3 < cap) pairs[(size_t)r.w * cap + p3] = make_int2(c.w, __float_as_int(v.w));
}

#define TA (NNZ_ADJ/4)   // 500000 threads for adj
#define TM (NNZ_MM/4)    //  75000 threads per modal graph

__global__ void bucket_all_kernel(const int4* __restrict__ ar, const int4* __restrict__ ac,
                                  const float4* __restrict__ av,
                                  const int4* __restrict__ ir, const int4* __restrict__ ic,
                                  const float4* __restrict__ iv,
                                  const int4* __restrict__ tr, const int4* __restrict__ tc,
                                  const float4* __restrict__ tv) {
    int t = blockIdx.x * blockDim.x + threadIdx.x;
    if (t < TA) {
        bucket4(ar[t], ac[t], av[t], g_cnt, g_adj_pairs, ADJ_CAP);
    } else if (t < TA + TM) {
        int e = t - TA;
        bucket4(ir[e], ic[e], iv[e], g_cnt + NT, g_img_pairs, MM_CAP);
    } else if (t < TA + 2 * TM) {
        int e = t - TA - TM;
        bucket4(tr[e], tc[e], tv[e], g_cnt + NT + NI, g_txt_pairs, MM_CAP);
    }
}

// ---------------- gather SPMM core: warp per row, float2 per lane, unroll 4 ----------------
__device__ __forceinline__ float2 gather_row(const int2* __restrict__ p, int cnt,
                                             const float* __restrict__ x, int lane) {
    float a0 = 0.f, a1 = 0.f;
    for (int base = 0; base < cnt; base += 32) {
        int j = base + lane;
        int2 pr = (j < cnt) ? p[j] : make_int2(0, 0);
        int m4 = (min(cnt - base, 32) + 3) & ~3;
        for (int k = 0; k < m4; k += 4) {
#pragma unroll
            for (int kk = 0; kk < 4; kk++) {
                int   col = __shfl_sync(0xffffffffu, pr.x, k + kk);
                float v   = __int_as_float(__shfl_sync(0xffffffffu, pr.y, k + kk));
                float2 xv = __ldg(reinterpret_cast<const float2*>(x + (size_t)col * DD) + lane);
                a0 = fmaf(v, xv.x, a0);
                a1 = fmaf(v, xv.y, a1);
            }
        }
    }
    return make_float2(a0, a1);
}

// ---------------- K2: adj layer 1 (warps [0,NT)) + modal gathers (warps [NT,NT+2NI)) ----
__global__ void k2_gather_kernel(const float* __restrict__ item_emb,
                                 float* __restrict__ out_img, float* __restrict__ out_txt) {
    int gw = (blockIdx.x * blockDim.x + threadIdx.x) >> 5;
    int lane = threadIdx.x & 31;
    if (gw < NT) {
        int cnt = min(g_cnt[gw], ADJ_CAP);
        float2 a = gather_row(g_adj_pairs + (size_t)gw * ADJ_CAP, cnt, g_ego, lane);
        reinterpret_cast<float2*>(g_cur1 + (size_t)gw * DD)[lane] = a;
    } else if (gw < NT + 2 * NI) {
        int w = gw - NT;
        bool is_img = w < NI;
        int row = is_img ? w : w - NI;
        int cnt = min(is_img ? g_cnt[NT + row] : g_cnt[NT + NI + row], MM_CAP);
        const int2* p = (is_img ? g_img_pairs : g_txt_pairs) + (size_t)row * MM_CAP;
        float2 a = gather_row(p, cnt, item_emb, lane);
        float* dst = (is_img ? out_img : out_txt) + (size_t)row * DD;
        reinterpret_cast<float2*>(dst)[lane] = a;
    }
}

// ---------------- warp MLP: q = tanh(x @ W + b) @ w2, broadcast to all lanes ----------------
__device__ __forceinline__ float mlp_query(float xlo, float xhi,
                                           const float* __restrict__ sW,
                                           const float* __restrict__ sb,
                                           const float* __restrict__ sw2, int lane) {
    float t0 = sb[lane];
    float t1 = sb[lane + 32];
#pragma unroll
    for (int k = 0; k < 32; k++) {
        float xv = __shfl_sync(0xffffffffu, xlo, k);
        t0 = fmaf(xv, sW[k * 64 + lane], t0);
        t1 = fmaf(xv, sW[k * 64 + lane + 32], t1);
    }
#pragma unroll
    for (int k = 0; k < 32; k++) {
        float xv = __shfl_sync(0xffffffffu, xhi, k);
        t0 = fmaf(xv, sW[(k + 32) * 64 + lane], t0);
        t1 = fmaf(xv, sW[(k + 32) * 64 + lane + 32], t1);
    }
    float q = tanhf(t0) * sw2[lane] + tanhf(t1) * sw2[lane + 32];
#pragma unroll
    for (int o = 16; o > 0; o >>= 1) q += __shfl_xor_sync(0xffffffffu, q, o);
    return q;
}

// ---------------- K3: adj layer 2 + final average (blocks [0,BA)) ; fuse_mm (blocks [BA,BA+BF)) ----
#define BA ((NT + 7) / 8)
#define BF 1024

__global__ void k3_kernel(const float* __restrict__ item_emb, float* __restrict__ ug,
                          const float* __restrict__ img, const float* __restrict__ txt,
                          const float* __restrict__ Wq1, const float* __restrict__ bq1,
                          const float* __restrict__ wq2, float* __restrict__ h_out) {
    int lane = threadIdx.x & 31;
    int warp = threadIdx.x >> 5;
    if (blockIdx.x < BA) {
        // adj layer 2 fused with final averaging
        int row = blockIdx.x * 8 + warp;
        if (row >= NT) return;
        int cnt = min(g_cnt[row], ADJ_CAP);
        float2 s = gather_row(g_adj_pairs + (size_t)row * ADJ_CAP, cnt, g_cur1, lane);
        const float kk = 1.f / 3.f;
        size_t g = (size_t)row * DD;
        float2 c = reinterpret_cast<const float2*>(g_cur1 + g)[lane];
        float2 e = reinterpret_cast<const float2*>(g_ego + g)[lane];
        float2 r = make_float2((e.x + c.x + s.x) * kk, (e.y + c.y + s.y) * kk);
        if (row < NU) {
            reinterpret_cast<float2*>(ug + g)[lane] = r;
        } else {
            reinterpret_cast<float2*>(g_ipre + (size_t)(row - NU) * DD)[lane] = r;
        }
    } else {
        // modal attention fusion (grid-stride over items)
        __shared__ float sW[64 * 64];
        __shared__ float sb[64];
        __shared__ float sw2[64];
        for (int i = threadIdx.x; i < 4096; i += blockDim.x) sW[i] = Wq1[i];
        if (threadIdx.x < 64) { sb[threadIdx.x] = bq1[threadIdx.x]; sw2[threadIdx.x] = wq2[threadIdx.x]; }
        __syncthreads();
        int w0id = (blockIdx.x - BA) * 8 + warp;
        for (int item = w0id; item < NI; item += BF * 8) {
            const float* ir = img + (size_t)item * DD;
            const float* tr = txt + (size_t)item * DD;
            float i0 = ir[lane], i1 = ir[lane + 32];
            float t0 = tr[lane], t1 = tr[lane + 32];
            float qi = mlp_query(i0, i1, sW, sb, sw2, lane);
            float qt = mlp_query(t0, t1, sW, sb, sw2, lane);
            float m = fmaxf(qi, qt);
            float e0 = __expf(qi - m), e1 = __expf(qt - m);
            float sinv = 1.f / (e0 + e1);
            float wa = e0 * sinv, wb = e1 * sinv;
            float h0 = wa * i0 + wb * t0;
            float h1 = wa * i1 + wb * t1;
            float ss = h0 * h0 + h1 * h1;
#pragma unroll
            for (int o = 16; o > 0; o >>= 1) ss += __shfl_xor_sync(0xffffffffu, ss, o);
            float rinv = 1.f / fmaxf(sqrtf(ss), 1e-12f);
            h_out[(size_t)item * DD + lane]      = h0;
            h_out[(size_t)item * DD + lane + 32] = h1;
            g_hnorm[(size_t)item * DD + lane]      = h0 * rinv;
            g_hnorm[(size_t)item * DD + lane + 32] = h1 * rinv;
        }
    }
}

// ---------------- K4: final item rows: cross-attention of i_pre with h_norm ----------------
__global__ void item_final_kernel(const float* __restrict__ Wc1, const float* __restrict__ bc1,
                                  const float* __restrict__ wc2, float* __restrict__ ig) {
    __shared__ float sW[64 * 64];
    __shared__ float sb[64];
    __shared__ float sw2[64];
    for (int i = threadIdx.x; i < 4096; i += blockDim.x) sW[i] = Wc1[i];
    if (threadIdx.x < 64) { sb[threadIdx.x] = bc1[threadIdx.x]; sw2[threadIdx.x] = wc2[threadIdx.x]; }
    __syncthreads();

    int lane = threadIdx.x & 31;
    int warp = (blockIdx.x * blockDim.x + threadIdx.x) >> 5;
    int nwarps = (gridDim.x * blockDim.x) >> 5;
    for (int item = warp; item < NI; item += nwarps) {
        size_t li = (size_t)item * DD;
        float a0 = g_ipre[li + lane],  a1 = g_ipre[li + lane + 32];
        float n0 = g_hnorm[li + lane], n1 = g_hnorm[li + lane + 32];
        float q0 = mlp_query(a0, a1, sW, sb, sw2, lane);
        float q1 = mlp_query(n0, n1, sW, sb, sw2, lane);
        float m = fmaxf(q0, q1);
        float e0 = __expf(q0 - m), e1 = __expf(q1 - m);
        float sinv = 1.f / (e0 + e1);
        float w0 = e0 * sinv, w1 = e1 * sinv;
        ig[li + lane]      = w0 * a0 + w1 * n0;
        ig[li + lane + 32] = w0 * a1 + w1 * n1;
    }
}

extern "C" void kernel_launch(void* const* d_in, const int* in_sizes, int n_in,
                              void* d_out, int out_size) {
    const float* user_emb = (const float*)d_in[0];
    const float* item_emb = (const float*)d_in[1];
    const float* Wq1 = (const float*)d_in[2];
    const float* bq1 = (const float*)d_in[3];
    const float* wq2 = (const float*)d_in[4];
    const float* Wc1 = (const float*)d_in[5];
    const float* bc1 = (const float*)d_in[6];
    const float* wc2 = (const float*)d_in[7];
    const float* adj_vals = (const float*)d_in[8];
    const float* img_vals = (const float*)d_in[9];
    const float* txt_vals = (const float*)d_in[10];
    const int* adj_rows = (const int*)d_in[11];
    const int* adj_cols = (const int*)d_in[12];
    const int* img_rows = (const int*)d_in[13];
    const int* img_cols = (const int*)d_in[14];
    const int* txt_rows = (const int*)d_in[15];
    const int* txt_cols = (const int*)d_in[16];

    float* out = (float*)d_out;
    float* out_ug  = out + OFF_UG;
    float* out_ig  = out + OFF_IG;
    float* out_img = out + OFF_IMG;
    float* out_txt = out + OFF_TXT;
    float* out_h   = out + OFF_H;

    const int T = 256;

    // device symbol addresses
    float* ego; cudaGetSymbolAddress((void**)&ego, g_ego);
    int*   cnt; cudaGetSymbolAddress((void**)&cnt, g_cnt);

    // 0. zero counters + materialize ego (memset/memcpy nodes are graph-capturable)
    cudaMemsetAsync(cnt, 0, (NT + 2 * NI) * sizeof(int));
    cudaMemcpyAsync(ego, user_emb, (size_t)NU * DD * sizeof(float), cudaMemcpyDeviceToDevice);
    cudaMemcpyAsync(ego + (size_t)NU * DD, item_emb, (size_t)NI * DD * sizeof(float),
                    cudaMemcpyDeviceToDevice);

    // 1. bucket builds (all three graphs, one kernel, 4 edges/thread)
    {
        int nthreads = TA + 2 * TM;
        bucket_all_kernel<<<(nthreads + T - 1) / T, T>>>(
            (const int4*)adj_rows, (const int4*)adj_cols, (const float4*)adj_vals,
            (const int4*)img_rows, (const int4*)img_cols, (const float4*)img_vals,
            (const int4*)txt_rows, (const int4*)txt_cols, (const float4*)txt_vals);
    }

    // 2. adj layer 1 + modal gathers (one kernel)
    {
        int nwarps = NT + 2 * NI;
        k2_gather_kernel<<<(nwarps + 7) / 8, T>>>(item_emb, out_img, out_txt);
    }

    // 3. adj layer 2 + final average + modal fuse (one kernel)
    k3_kernel<<<BA + BF, T>>>(item_emb, out_ug, out_img, out_txt, Wq1, bq1, wq2, out_h);

    // 4. item cross-attention
    item_final_kernel<<<BF, T>>>(Wc1, bc1, wc2, out_ig);

    (void)in_sizes; (void)n_in; (void)out_size;
}

// round 4
// speedup vs baseline: 3.6988x; 3.6988x over previous
#include <cuda_runtime.h>

#define NU 80000
#define NI 30000
#define NT 110000   // NU + NI
#define DD 64
#define NNZ_ADJ 2000000
#define NNZ_MM  300000

#define ADJ_CAP 64   // Poisson(18.2) max-degree bound over 110K rows (>10 sigma)
#define MM_CAP  48   // Poisson(10.0) max-degree bound over 30K rows  (>10 sigma)

// out layout (float offsets)
#define OFF_UG   0
#define OFF_IG   (NU*DD)
#define OFF_IMG  (OFF_IG + NI*DD)
#define OFF_TXT  (OFF_IMG + NI*DD)
#define OFF_H    (OFF_TXT + NI*DD)

// ---------------- scratch (__device__ globals; no allocation allowed) ----------------
__device__ float g_ego[NT*DD];      // [user_emb ; item_emb]
__device__ float g_cur1[NT*DD];     // layer-1 adj output
__device__ float g_ipre[NI*DD];     // (ie + cur1 + cur2)/3 for items
__device__ float g_hnorm[NI*DD];

__device__ int  g_cnt[NT + 2*NI];   // adj | img | txt counters (single memset)
__device__ int2 g_adj_pairs[(size_t)NT * ADJ_CAP];
__device__ int2 g_img_pairs[(size_t)NI * MM_CAP];
__device__ int2 g_txt_pairs[(size_t)NI * MM_CAP];

// ---------------- bucket build: 4 edges per thread, 4 atomics in flight ----------------
__device__ __forceinline__ void bucket4(int4 r, int4 c, float4 v,
                                        int* __restrict__ counts, int2* __restrict__ pairs,
                                        int cap) {
    int p0 = atomicAdd(&counts[r.x], 1);
    int p1 = atomicAdd(&counts[r.y], 1);
    int p2 = atomicAdd(&counts[r.z], 1);
    int p3 = atomicAdd(&counts[r.w], 1);
    if (p0 < cap) pairs[(size_t)r.x * cap + p0] = make_int2(c.x, __float_as_int(v.x));
    if (p1 < cap) pairs[(size_t)r.y * cap + p1] = make_int2(c.y, __float_as_int(v.y));
    if (p2 < cap) pairs[(size_t)r.z * cap + p2] = make_int2(c.z, __float_as_int(v.z));
    if (p3 < cap) pairs[(size_t)r.w * cap + p3] = make_int2(c.w, __float_as_int(v.w));
}

#define TA (NNZ_ADJ/4)   // 500000 threads for adj
#define TM (NNZ_MM/4)    //  75000 threads per modal graph

__global__ __launch_bounds__(256) void bucket_all_kernel(
        const int4* __restrict__ ar, const int4* __restrict__ ac, const float4* __restrict__ av,
        const int4* __restrict__ ir, const int4* __restrict__ ic, const float4* __restrict__ iv,
        const int4* __restrict__ tr, const int4* __restrict__ tc, const float4* __restrict__ tv) {
    int t = blockIdx.x * blockDim.x + threadIdx.x;
    if (t < TA) {
        bucket4(ar[t], ac[t], av[t], g_cnt, g_adj_pairs, ADJ_CAP);
    } else if (t < TA + TM) {
        int e = t - TA;
        bucket4(ir[e], ic[e], iv[e], g_cnt + NT, g_img_pairs, MM_CAP);
    } else if (t < TA + 2 * TM) {
        int e = t - TA - TM;
        bucket4(tr[e], tc[e], tv[e], g_cnt + NT + NI, g_txt_pairs, MM_CAP);
    }
}

// ---------------- gather SPMM core: warp per row, float2 per lane, unroll 4 ----------------
__device__ __forceinline__ float2 gather_row(const int2* __restrict__ p, int cnt,
                                             const float* __restrict__ x, int lane) {
    float a0 = 0.f, a1 = 0.f;
    for (int base = 0; base < cnt; base += 32) {
        int j = base + lane;
        int2 pr = (j < cnt) ? p[j] : make_int2(0, 0);
        int m4 = (min(cnt - base, 32) + 3) & ~3;
        for (int k = 0; k < m4; k += 4) {
#pragma unroll
            for (int kk = 0; kk < 4; kk++) {
                int   col = __shfl_sync(0xffffffffu, pr.x, k + kk);
                float v   = __int_as_float(__shfl_sync(0xffffffffu, pr.y, k + kk));
                float2 xv = __ldg(reinterpret_cast<const float2*>(x + (size_t)col * DD) + lane);
                a0 = fmaf(v, xv.x, a0);
                a1 = fmaf(v, xv.y, a1);
            }
        }
    }
    return make_float2(a0, a1);
}

// ---------------- K2: adj layer 1 (warps [0,NT)) + modal gathers (warps [NT,NT+2NI)) ----
__global__ __launch_bounds__(256) void k2_gather_kernel(const float* __restrict__ item_emb,
                                 float* __restrict__ out_img, float* __restrict__ out_txt) {
    int gw = (blockIdx.x * blockDim.x + threadIdx.x) >> 5;
    int lane = threadIdx.x & 31;
    if (gw < NT) {
        int cnt = min(g_cnt[gw], ADJ_CAP);
        float2 a = gather_row(g_adj_pairs + (size_t)gw * ADJ_CAP, cnt, g_ego, lane);
        reinterpret_cast<float2*>(g_cur1 + (size_t)gw * DD)[lane] = a;
    } else if (gw < NT + 2 * NI) {
        int w = gw - NT;
        bool is_img = w < NI;
        int row = is_img ? w : w - NI;
        int cnt = min(is_img ? g_cnt[NT + row] : g_cnt[NT + NI + row], MM_CAP);
        const int2* p = (is_img ? g_img_pairs : g_txt_pairs) + (size_t)row * MM_CAP;
        float2 a = gather_row(p, cnt, item_emb, lane);
        float* dst = (is_img ? out_img : out_txt) + (size_t)row * DD;
        reinterpret_cast<float2*>(dst)[lane] = a;
    }
}

// ---------------- K3: adj layer 2 + final averaging (standalone, low regs) ----------------
__global__ __launch_bounds__(256) void adj2_final_kernel(float* __restrict__ ug) {
    int row = (blockIdx.x * blockDim.x + threadIdx.x) >> 5;
    int lane = threadIdx.x & 31;
    if (row >= NT) return;
    int cnt = min(g_cnt[row], ADJ_CAP);
    float2 s = gather_row(g_adj_pairs + (size_t)row * ADJ_CAP, cnt, g_cur1, lane);
    const float kk = 1.f / 3.f;
    size_t g = (size_t)row * DD;
    float2 c = reinterpret_cast<const float2*>(g_cur1 + g)[lane];
    float2 e = reinterpret_cast<const float2*>(g_ego + g)[lane];
    float2 r = make_float2((e.x + c.x + s.x) * kk, (e.y + c.y + s.y) * kk);
    if (row < NU) {
        reinterpret_cast<float2*>(ug + g)[lane] = r;
    } else {
        reinterpret_cast<float2*>(g_ipre + (size_t)(row - NU) * DD)[lane] = r;
    }
}

// ============================================================================
// Warp-batched MLP core: 4 items x 2 queries per warp.
// Lane l accumulates hidden units (2l, 2l+1) for 8 input vectors at once.
// W is read once per k as a single LDS.64 shared across 16 FMAs.
// After the k-loop each lane contributes tanh(.)-weighted pairs; warp-reduce
// gives all 8 scalar query values broadcast to every lane.
// ============================================================================
struct MlpSmem {
    float2 Wp[2048];    // W[k][2l],W[k][2l+1] at [k*32+l]  (identical layout to row-major W)
    float2 bp[32];
    float2 w2p[32];
    float  x[8][8][64]; // [warp][vector][k]
};

__device__ __forceinline__ void mlp_load_weights(MlpSmem* s, const float* __restrict__ W,
                                                 const float* __restrict__ b,
                                                 const float* __restrict__ w2) {
    const float2* Wg = reinterpret_cast<const float2*>(W);
    for (int i = threadIdx.x; i < 2048; i += blockDim.x) s->Wp[i] = Wg[i];
    if (threadIdx.x < 32) {
        s->bp[threadIdx.x]  = reinterpret_cast<const float2*>(b)[threadIdx.x];
        s->w2p[threadIdx.x] = reinterpret_cast<const float2*>(w2)[threadIdx.x];
    }
    __syncthreads();
}

// computes qv[0..7] (broadcast to all lanes) for the 8 vectors staged in s->x[w]
__device__ __forceinline__ void mlp_eval8(const MlpSmem* s, int w, int lane, float* qv) {
    float2 acc[8];
    float2 b2 = s->bp[lane];
#pragma unroll
    for (int q = 0; q < 8; q++) acc[q] = b2;
#pragma unroll 4
    for (int k = 0; k < 64; k++) {
        float2 wv = s->Wp[k * 32 + lane];
#pragma unroll
        for (int q = 0; q < 8; q++) {
            float xk = s->x[w][q][k];
            acc[q].x = fmaf(xk, wv.x, acc[q].x);
            acc[q].y = fmaf(xk, wv.y, acc[q].y);
        }
    }
    float2 w2v = s->w2p[lane];
#pragma unroll
    for (int q = 0; q < 8; q++) {
        float c = tanhf(acc[q].x) * w2v.x + tanhf(acc[q].y) * w2v.y;
#pragma unroll
        for (int o = 16; o > 0; o >>= 1) c += __shfl_xor_sync(0xffffffffu, c, o);
        qv[q] = c;
    }
}

// ---------------- K4: modal attention fusion -> h, h_norm ----------------
__global__ __launch_bounds__(256) void fuse_mm_kernel(const float* __restrict__ img,
                                                      const float* __restrict__ txt,
                                                      const float* __restrict__ Wq1,
                                                      const float* __restrict__ bq1,
                                                      const float* __restrict__ wq2,
                                                      float* __restrict__ h_out) {
    __shared__ MlpSmem s;
    mlp_load_weights(&s, Wq1, bq1, wq2);
    int w = threadIdx.x >> 5, lane = threadIdx.x & 31;
    int base = (blockIdx.x * 8 + w) * 4;
    if (base >= NI) return;
#pragma unroll
    for (int t = 0; t < 4; t++) {
        int it = min(base + t, NI - 1);
        const float* ir = img + (size_t)it * DD;
        const float* tr = txt + (size_t)it * DD;
        s.x[w][t][lane]          = ir[lane];
        s.x[w][t][lane + 32]     = ir[lane + 32];
        s.x[w][t + 4][lane]      = tr[lane];
        s.x[w][t + 4][lane + 32] = tr[lane + 32];
    }
    __syncwarp();
    float qv[8];
    mlp_eval8(&s, w, lane, qv);
#pragma unroll
    for (int t = 0; t < 4; t++) {
        int it = base + t;
        if (it >= NI) break;
        float m = fmaxf(qv[t], qv[t + 4]);
        float e0 = __expf(qv[t] - m), e1 = __expf(qv[t + 4] - m);
        float sinv = 1.f / (e0 + e1);
        float w0 = e0 * sinv, w1 = e1 * sinv;
        float i0 = s.x[w][t][lane],     i1 = s.x[w][t][lane + 32];
        float t0 = s.x[w][t + 4][lane], t1 = s.x[w][t + 4][lane + 32];
        float h0 = w0 * i0 + w1 * t0;
        float h1 = w0 * i1 + w1 * t1;
        float ss = h0 * h0 + h1 * h1;
#pragma unroll
        for (int o = 16; o > 0; o >>= 1) ss += __shfl_xor_sync(0xffffffffu, ss, o);
        float rinv = 1.f / fmaxf(sqrtf(ss), 1e-12f);
        h_out[(size_t)it * DD + lane]      = h0;
        h_out[(size_t)it * DD + lane + 32] = h1;
        g_hnorm[(size_t)it * DD + lane]      = h0 * rinv;
        g_hnorm[(size_t)it * DD + lane + 32] = h1 * rinv;
    }
}

// ---------------- K5: item cross-attention of i_pre with h_norm -> ig ----------------
__global__ __launch_bounds__(256) void item_final_kernel(const float* __restrict__ Wc1,
                                                         const float* __restrict__ bc1,
                                                         const float* __restrict__ wc2,
                                                         float* __restrict__ ig) {
    __shared__ MlpSmem s;
    mlp_load_weights(&s, Wc1, bc1, wc2);
    int w = threadIdx.x >> 5, lane = threadIdx.x & 31;
    int base = (blockIdx.x * 8 + w) * 4;
    if (base >= NI) return;
#pragma unroll
    for (int t = 0; t < 4; t++) {
        int it = min(base + t, NI - 1);
        const float* ar = g_ipre + (size_t)it * DD;
        const float* nr = g_hnorm + (size_t)it * DD;
        s.x[w][t][lane]          = ar[lane];
        s.x[w][t][lane + 32]     = ar[lane + 32];
        s.x[w][t + 4][lane]      = nr[lane];
        s.x[w][t + 4][lane + 32] = nr[lane + 32];
    }
    __syncwarp();
    float qv[8];
    mlp_eval8(&s, w, lane, qv);
#pragma unroll
    for (int t = 0; t < 4; t++) {
        int it = base + t;
        if (it >= NI) break;
        float m = fmaxf(qv[t], qv[t + 4]);
        float e0 = __expf(qv[t] - m), e1 = __expf(qv[t + 4] - m);
        float sinv = 1.f / (e0 + e1);
        float w0 = e0 * sinv, w1 = e1 * sinv;
        float a0 = s.x[w][t][lane],     a1 = s.x[w][t][lane + 32];
        float n0 = s.x[w][t + 4][lane], n1 = s.x[w][t + 4][lane + 32];
        ig[(size_t)it * DD + lane]      = w0 * a0 + w1 * n0;
        ig[(size_t)it * DD + lane + 32] = w0 * a1 + w1 * n1;
    }
}

extern "C" void kernel_launch(void* const* d_in, const int* in_sizes, int n_in,
                              void* d_out, int out_size) {
    const float* user_emb = (const float*)d_in[0];
    const float* item_emb = (const float*)d_in[1];
    const float* Wq1 = (const float*)d_in[2];
    const float* bq1 = (const float*)d_in[3];
    const float* wq2 = (const float*)d_in[4];
    const float* Wc1 = (const float*)d_in[5];
    const float* bc1 = (const float*)d_in[6];
    const float* wc2 = (const float*)d_in[7];
    const float* adj_vals = (const float*)d_in[8];
    const float* img_vals = (const float*)d_in[9];
    const float* txt_vals = (const float*)d_in[10];
    const int* adj_rows = (const int*)d_in[11];
    const int* adj_cols = (const int*)d_in[12];
    const int* img_rows = (const int*)d_in[13];
    const int* img_cols = (const int*)d_in[14];
    const int* txt_rows = (const int*)d_in[15];
    const int* txt_cols = (const int*)d_in[16];

    float* out = (float*)d_out;
    float* out_ug  = out + OFF_UG;
    float* out_ig  = out + OFF_IG;
    float* out_img = out + OFF_IMG;
    float* out_txt = out + OFF_TXT;
    float* out_h   = out + OFF_H;

    const int T = 256;

    float* ego; cudaGetSymbolAddress((void**)&ego, g_ego);
    int*   cnt; cudaGetSymbolAddress((void**)&cnt, g_cnt);

    // 0. zero counters + materialize ego
    cudaMemsetAsync(cnt, 0, (NT + 2 * NI) * sizeof(int));
    cudaMemcpyAsync(ego, user_emb, (size_t)NU * DD * sizeof(float), cudaMemcpyDeviceToDevice);
    cudaMemcpyAsync(ego + (size_t)NU * DD, item_emb, (size_t)NI * DD * sizeof(float),
                    cudaMemcpyDeviceToDevice);

    // 1. bucket builds (all three graphs, one kernel, 4 edges/thread)
    {
        int nthreads = TA + 2 * TM;
        bucket_all_kernel<<<(nthreads + T - 1) / T, T>>>(
            (const int4*)adj_rows, (const int4*)adj_cols, (const float4*)adj_vals,
            (const int4*)img_rows, (const int4*)img_cols, (const float4*)img_vals,
            (const int4*)txt_rows, (const int4*)txt_cols, (const float4*)txt_vals);
    }

    // 2. adj layer 1 + modal gathers (one kernel, low regs)
    {
        int nwarps = NT + 2 * NI;
        k2_gather_kernel<<<(nwarps + 7) / 8, T>>>(item_emb, out_img, out_txt);
    }

    // 3. modal attention fusion (4 items x 8 warps per block)
    fuse_mm_kernel<<<(NI + 31) / 32, T>>>(out_img, out_txt, Wq1, bq1, wq2, out_h);

    // 4. adj layer 2 + final averaging
    adj2_final_kernel<<<(NT + 7) / 8, T>>>(out_ug);

    // 5. item cross-attention
    item_final_kernel<<<(NI + 31) / 32, T>>>(Wc1, bc1, wc2, out_ig);

    (void)in_sizes; (void)n_in; (void)out_size;
}